// round 10
// baseline (speedup 1.0000x reference)
#include <cuda_runtime.h>
#include <cuda_bf16.h>

#define TT 2048
#define BB 64
#define GG 192
#define OUT_MAIN 33554432
#define NTILE 8192

typedef unsigned long long ull;

// ---------------- device scratch (no cudaMalloc allowed) ----------------
__device__ float g_gi[(size_t)TT * BB * 768];          // input-side preactivations
__device__ ulonglong2 g_wihA[64 * 96];                 // {(r pair),(i pair)} per (u, col-pair)
__device__ ulonglong2 g_wihB[64 * 96];                 // {(j pair),(k pair)}
__device__ ulonglong2 g_whhA[64 * 96];
__device__ ulonglong2 g_whhB[64 * 96];
__device__ ulonglong2 g_whhS[64 * 96];                 // {(wr+wi pair),(wj+wk pair)}

// ---------------- helpers ----------------
__device__ __forceinline__ ull pk2(float a, float b) {
    ull r; asm("mov.b64 %0, {%1,%2};" : "=l"(r) : "f"(a), "f"(b)); return r;
}
__device__ __forceinline__ float2 upk2(ull v) {
    float2 r; asm("mov.b64 {%0,%1}, %2;" : "=f"(r.x), "=f"(r.y) : "l"(v)); return r;
}
__device__ __forceinline__ unsigned s2u(const void* p) {
    unsigned a;
    asm("{ .reg .u64 t; cvta.to.shared.u64 t, %1; cvt.u32.u64 %0, t; }" : "=r"(a) : "l"(p));
    return a;
}
#define FMA2(acc, a, b) asm("fma.rn.f32x2 %0, %1, %2, %0;" : "+l"(acc) : "l"(a), "l"(b))

// 16-FMA Hamilton scheme (GEMM path)
#define QFMA16(hr2,hi2,hj2,hk2, wr2,wi2,wj2,wk2, Pr,Nr,Pi,Ni,Pj,Nj,Pk,Nk) do { \
    FMA2(Pr,hr2,wr2); FMA2(Nr,hi2,wi2); FMA2(Nr,hj2,wj2); FMA2(Nr,hk2,wk2);    \
    FMA2(Pi,hr2,wi2); FMA2(Pi,hi2,wr2); FMA2(Pi,hk2,wj2); FMA2(Ni,hj2,wk2);    \
    FMA2(Pj,hr2,wj2); FMA2(Pj,hi2,wk2); FMA2(Pj,hj2,wr2); FMA2(Nj,hk2,wi2);    \
    FMA2(Pk,hr2,wk2); FMA2(Pk,hj2,wi2); FMA2(Pk,hk2,wr2); FMA2(Nk,hi2,wj2);    \
} while (0)

__device__ __forceinline__ float sig_f(float x) {
    return 1.0f / (1.0f + __expf(-x));
}
__device__ __forceinline__ float tanh_f(float x) {
    float e = __expf(2.0f * x);
    return 1.0f - 2.0f / (e + 1.0f);
}

// ---------------- weight packing ----------------
__global__ void qrn_prep(const float* __restrict__ wihr, const float* __restrict__ wihi,
                         const float* __restrict__ wihj, const float* __restrict__ wihk,
                         const float* __restrict__ whhr, const float* __restrict__ whhi,
                         const float* __restrict__ whhj, const float* __restrict__ whhk) {
    int idx = blockIdx.x * blockDim.x + threadIdx.x;
    if (idx >= 64 * 96) return;
    int u = idx / 96, jp = idx % 96;
    int c0 = u * GG + 2 * jp;
    ulonglong2 a, bv, s;
    a.x  = pk2(wihr[c0], wihr[c0 + 1]); a.y  = pk2(wihi[c0], wihi[c0 + 1]);
    bv.x = pk2(wihj[c0], wihj[c0 + 1]); bv.y = pk2(wihk[c0], wihk[c0 + 1]);
    g_wihA[idx] = a; g_wihB[idx] = bv;
    a.x  = pk2(whhr[c0], whhr[c0 + 1]); a.y  = pk2(whhi[c0], whhi[c0 + 1]);
    bv.x = pk2(whhj[c0], whhj[c0 + 1]); bv.y = pk2(whhk[c0], whhk[c0 + 1]);
    g_whhA[idx] = a; g_whhB[idx] = bv;
    s.x = pk2(whhr[c0] + whhi[c0], whhr[c0 + 1] + whhi[c0 + 1]);
    s.y = pk2(whhj[c0] + whhk[c0], whhj[c0 + 1] + whhk[c0 + 1]);
    g_whhS[idx] = s;
}

// ---------------- phase 1: gi = x @ W_ih + b_ih (full chip, serial) ----------------
#define GEMM_SMEM (98304 * 2 + 16384)
__global__ __launch_bounds__(384, 1) void qrn_gemm(const float* __restrict__ x,
                                                   const float* __restrict__ bih) {
    extern __shared__ char smem[];
    ulonglong2* swA = (ulonglong2*)smem;
    ulonglong2* swB = (ulonglong2*)(smem + 98304);
    float* xs = (float*)(smem + 196608);
    int t = threadIdx.x;
    for (int i = t; i < 6144; i += 384) { swA[i] = g_wihA[i]; swB[i] = g_wihB[i]; }
    int jp = t % 96, rg = t / 96;
    float2 bias2[4];
#pragma unroll
    for (int q = 0; q < 4; ++q) bias2[q] = *(const float2*)(bih + q * GG + 2 * jp);

    for (int tile = blockIdx.x; tile < NTILE; tile += gridDim.x) {
        __syncthreads();
        const float4* xt4 = (const float4*)(x + (size_t)tile * 4096);
        float4* xs4 = (float4*)xs;
        for (int i = t; i < 1024; i += 384) xs4[i] = xt4[i];
        __syncthreads();

        ull acc[4][8];
#pragma unroll
        for (int rr = 0; rr < 4; ++rr)
#pragma unroll
            for (int k = 0; k < 8; ++k) acc[rr][k] = 0ull;

#pragma unroll 4
        for (int u = 0; u < 64; ++u) {
            ulonglong2 wA = swA[u * 96 + jp];
            ulonglong2 wB = swB[u * 96 + jp];
#pragma unroll
            for (int rr = 0; rr < 4; ++rr) {
                const float* xr = xs + (rg * 4 + rr) * 256 + u;
                float hr = xr[0], hi = xr[64], hj = xr[128], hk = xr[192];
                ull hr2 = pk2(hr, hr), hi2 = pk2(hi, hi);
                ull hj2 = pk2(hj, hj), hk2 = pk2(hk, hk);
                QFMA16(hr2, hi2, hj2, hk2, wA.x, wA.y, wB.x, wB.y,
                       acc[rr][0], acc[rr][1], acc[rr][2], acc[rr][3],
                       acc[rr][4], acc[rr][5], acc[rr][6], acc[rr][7]);
            }
        }

#pragma unroll
        for (int rr = 0; rr < 4; ++rr) {
            float* go = g_gi + ((size_t)tile * 16 + rg * 4 + rr) * 768;
#pragma unroll
            for (int q = 0; q < 4; ++q) {
                float2 p = upk2(acc[rr][2 * q]);
                float2 n = upk2(acc[rr][2 * q + 1]);
                float2 o;
                o.x = p.x - n.x + bias2[q].x;
                o.y = p.y - n.y + bias2[q].y;
                *(float2*)(go + q * GG + 2 * jp) = o;
            }
        }
    }
}

// ---------------- phase 2: recurrence, 2-CTA cluster per batch (K-split) ----------------
// 12-mult Karatsuba quaternion scheme:
//   M1=hr*wr M2=hi*wi M3=(hr+hi)(wr+wi) M4=hj*wj M5=hk*wk M6=(hj-hk)(wj+wk)
//   M7=hr*wj M8=hi*wk M9=(hr-hi)(wj+wk) M10=hj*wr M11=hk*wi M12=(hj+hk)(wr+wi)
//   out_r = M1-M2-M4-M5
//   out_i = M3-M1-M2-M6+M4-M5
//   out_j = M7+M8+M10-M11
//   out_k = M9-M7+M8+M12-M10-M11
// Weight base slots {wr,wi},{wj,wk} in regs; sum slots {wr+wi,wj+wk} in smem.
// h factor record per unit u (16 floats, dup pairs):
//   [hr hr hi hi | hj hj hk hk | s1 s1 d1 d1 | s2 s2 d2 d2], s1=hr+hi d1=hr-hi s2=hj+hk d2=hj-hk
// Owner layout: t<256, q=t&3, u=t>>2 (all 4 components of u in one warp -> shfl)
// red/pbuf use 200-float q-stride (bank-conflict-free for this layout).
#define REC_SMEM 73728
#define OFF_RED   49152
#define OFF_PBUF  61952
#define OFF_H4F   68352
#define OFF_MBAR  72448

__global__ __launch_bounds__(384, 1) __cluster_dims__(2, 1, 1)
void qrn_recur(const float* __restrict__ hx, const float* __restrict__ bhh,
               float* __restrict__ out, int out_size) {
    extern __shared__ char smem[];
    ulonglong2* sumW = (ulonglong2*)smem;                 // 48KB: local 32u x 96cp
    float* red  = (float*)(smem + OFF_RED);               // 12.8KB: 4 parts x 800
    float* pbuf = (float*)(smem + OFF_PBUF);              // 6.4KB: 2 parity x 800
    float* h4f  = (float*)(smem + OFF_H4F);               // 4KB: 64u x 16 factors
    ull*   mbar = (ull*)(smem + OFF_MBAR);

    int t = threadIdx.x;
    unsigned rank;
    asm("mov.u32 %0, %%cluster_ctarank;" : "=r"(rank));
    int b = blockIdx.x >> 1;
    int jp = t % 96, up = t / 96, ub = up * 8;
    int ru = (int)rank * 32;

    // register-resident base weight slots
    ulonglong2 wAr[8], wBr[8];
#pragma unroll
    for (int uu = 0; uu < 8; ++uu) {
        wAr[uu] = g_whhA[(ru + ub + uu) * 96 + jp];
        wBr[uu] = g_whhB[(ru + ub + uu) * 96 + jp];
    }
    // sum slots -> smem
    for (int i = t; i < 3072; i += 384)
        sumW[i] = g_whhS[(ru + i / 96) * 96 + (i % 96)];

    unsigned mbar_u = s2u(mbar);
    unsigned pbuf_u = s2u(pbuf);
    unsigned peer = rank ^ 1u;
    unsigned peer_mbar, peer_pbuf;
    asm("mapa.shared::cluster.u32 %0, %1, %2;" : "=r"(peer_mbar) : "r"(mbar_u), "r"(peer));
    asm("mapa.shared::cluster.u32 %0, %1, %2;" : "=r"(peer_pbuf) : "r"(pbuf_u), "r"(peer));

    float hcur = 0.f, bh0 = 0.f, bh1 = 0.f, bh2 = 0.f;
    int q = 0, u = 0;
    if (t < 256) {
        q = t & 3; u = t >> 2;
        int o0g = q * GG + u;
        hcur = hx[b * 256 + q * 64 + u];
        bh0 = bhh[o0g]; bh1 = bhh[o0g + 64]; bh2 = bhh[o0g + 128];
        // initial h factor record
        float hp = __shfl_xor_sync(0xFFFFFFFFu, hcur, 1);
        float2 hd; hd.x = hcur; hd.y = hcur;
        *(float2*)(h4f + u * 16 + 2 * q) = hd;
        if ((q & 1) == 0) {
            float s = hcur + hp, d = hcur - hp;
            int base = u * 16 + 8 + ((q == 2) ? 4 : 0);
            float2 sv; sv.x = s; sv.y = s;
            float2 dv; dv.x = d; dv.y = d;
            *(float2*)(h4f + base)     = sv;
            *(float2*)(h4f + base + 2) = dv;
        }
    }
    if (t == 0)
        asm volatile("mbarrier.init.shared.b64 [%0], %1;" :: "r"(mbar_u), "r"(256u) : "memory");
    __syncthreads();
    asm volatile("barrier.cluster.arrive.aligned;" ::: "memory");
    asm volatile("barrier.cluster.wait.aligned;" ::: "memory");

    // preload gi[0]
    float gc0 = 0.f, gc1 = 0.f, gc2 = 0.f;
    if (t < 256) {
        const float* gp = g_gi + (size_t)b * 768 + q * GG + u;
        gc0 = gp[0]; gc1 = gp[64]; gc2 = gp[128];
    }

#pragma unroll 1
    for (int step = 0; step < TT; ++step) {
        unsigned par = (unsigned)step & 1u;
        // prefetch gi[step+1] (covered by the whole step)
        float gn0 = 0.f, gn1 = 0.f, gn2 = 0.f;
        if (t < 256 && step + 1 < TT) {
            const float* gp = g_gi + ((size_t)(step + 1) * BB + b) * 768 + q * GG + u;
            gn0 = __ldcg(gp); gn1 = __ldcg(gp + 64); gn2 = __ldcg(gp + 128);
        }

        ull M1 = 0, M2 = 0, M3 = 0, M4 = 0, M5 = 0, M6 = 0;
        ull M7 = 0, M8 = 0, M9 = 0, M10 = 0, M11 = 0, M12 = 0;
#pragma unroll
        for (int uu = 0; uu < 8; ++uu) {
            int gu = ru + ub + uu;
            int lu = ub + uu;
            ulonglong2 hA = *(ulonglong2*)(h4f + gu * 16);       // {hr,hr,hi,hi}
            ulonglong2 hB = *(ulonglong2*)(h4f + gu * 16 + 4);   // {hj,hj,hk,hk}
            ulonglong2 hC = *(ulonglong2*)(h4f + gu * 16 + 8);   // {s1,s1,d1,d1}
            ulonglong2 hD = *(ulonglong2*)(h4f + gu * 16 + 12);  // {s2,s2,d2,d2}
            ulonglong2 wS = sumW[lu * 96 + jp];                  // {wr+wi, wj+wk}
            FMA2(M1,  hA.x, wAr[uu].x);
            FMA2(M2,  hA.y, wAr[uu].y);
            FMA2(M3,  hC.x, wS.x);
            FMA2(M4,  hB.x, wBr[uu].x);
            FMA2(M5,  hB.y, wBr[uu].y);
            FMA2(M6,  hD.y, wS.y);
            FMA2(M7,  hA.x, wBr[uu].x);
            FMA2(M8,  hA.y, wBr[uu].y);
            FMA2(M9,  hC.y, wS.y);
            FMA2(M10, hB.x, wAr[uu].x);
            FMA2(M11, hB.y, wAr[uu].y);
            FMA2(M12, hD.x, wS.x);
        }
        {
            float2 m1 = upk2(M1), m2 = upk2(M2), m3 = upk2(M3), m4 = upk2(M4);
            float2 m5 = upk2(M5), m6 = upk2(M6), m7 = upk2(M7), m8 = upk2(M8);
            float2 m9 = upk2(M9), m10 = upk2(M10), m11 = upk2(M11), m12 = upk2(M12);
            float2 vr, vi, vj, vk;
            vr.x = m1.x - m2.x - m4.x - m5.x;
            vr.y = m1.y - m2.y - m4.y - m5.y;
            vi.x = m3.x - m1.x - m2.x - m6.x + m4.x - m5.x;
            vi.y = m3.y - m1.y - m2.y - m6.y + m4.y - m5.y;
            vj.x = m7.x + m8.x + m10.x - m11.x;
            vj.y = m7.y + m8.y + m10.y - m11.y;
            vk.x = m9.x - m7.x + m8.x + m12.x - m10.x - m11.x;
            vk.y = m9.y - m7.y + m8.y + m12.y - m10.y - m11.y;
            float* rb = red + up * 800 + 2 * jp;
            *(float2*)(rb)       = vr;
            *(float2*)(rb + 200) = vi;
            *(float2*)(rb + 400) = vj;
            *(float2*)(rb + 600) = vk;
        }
        __syncthreads();

        if (t < 256) {
            int o0 = q * 200 + u;
            // local half-sums for this output's 3 gates
            float p0 = red[o0]       + red[800 + o0]       + red[1600 + o0]       + red[2400 + o0];
            float p1 = red[o0 + 64]  + red[800 + o0 + 64]  + red[1600 + o0 + 64]  + red[2400 + o0 + 64];
            float p2 = red[o0 + 128] + red[800 + o0 + 128] + red[1600 + o0 + 128] + red[2400 + o0 + 128];
            // ship to peer (parity-buffered), then signal peer's mbar (release)
            unsigned dst = peer_pbuf + ((par * 800u + (unsigned)o0) << 2);
            asm volatile("st.shared::cluster.b32 [%0], %1;" :: "r"(dst),        "r"(__float_as_uint(p0)) : "memory");
            asm volatile("st.shared::cluster.b32 [%0], %1;" :: "r"(dst + 256u), "r"(__float_as_uint(p1)) : "memory");
            asm volatile("st.shared::cluster.b32 [%0], %1;" :: "r"(dst + 512u), "r"(__float_as_uint(p2)) : "memory");
            asm volatile("mbarrier.arrive.release.cluster.shared::cluster.b64 _, [%0];"
                         :: "r"(peer_mbar) : "memory");
            // wait for peer's 256 arrivals on local mbar (acquire.cta: flag+data local)
            unsigned done = 0;
            while (!done)
                asm volatile("{ .reg .pred p; "
                             "mbarrier.try_wait.parity.acquire.cta.shared::cta.b64 p, [%1], %2, 0x989680; "
                             "selp.b32 %0, 1, 0, p; }"
                             : "=r"(done) : "r"(mbar_u), "r"(par) : "memory");
            const float* pb = pbuf + par * 800;
            float gh0 = p0 + pb[o0];
            float gh1 = p1 + pb[o0 + 64];
            float gh2 = p2 + pb[o0 + 128];
            float rg_ = sig_f(gc0 + gh0 + bh0);
            float zg  = sig_f(gc1 + gh1 + bh1);
            float ng  = tanh_f(gc2 + rg_ * (gh2 + bh2));
            hcur = ng + zg * (hcur - ng);
            if (rank == 0)
                out[((size_t)step * BB + b) * 256 + q * 64 + u] = hcur;
            // rebuild h factor record (shfl within quad)
            float hp = __shfl_xor_sync(0xFFFFFFFFu, hcur, 1);
            float2 hd; hd.x = hcur; hd.y = hcur;
            *(float2*)(h4f + u * 16 + 2 * q) = hd;
            if ((q & 1) == 0) {
                float s = hcur + hp, d = hcur - hp;
                int base = u * 16 + 8 + ((q == 2) ? 4 : 0);
                float2 sv; sv.x = s; sv.y = s;
                float2 dv; dv.x = d; dv.y = d;
                *(float2*)(h4f + base)     = sv;
                *(float2*)(h4f + base + 2) = dv;
            }
        }
        gc0 = gn0; gc1 = gn1; gc2 = gn2;
        __syncthreads();
    }

    if (rank == 0 && t < 256 && out_size >= OUT_MAIN + BB * 256)
        out[OUT_MAIN + b * 256 + q * 64 + u] = hcur;

    asm volatile("barrier.cluster.arrive.aligned;" ::: "memory");
    asm volatile("barrier.cluster.wait.aligned;" ::: "memory");
}

extern "C" void kernel_launch(void* const* d_in, const int* in_sizes, int n_in,
                              void* d_out, int out_size) {
    const float* x    = (const float*)d_in[0];
    const float* hx   = (const float*)d_in[1];
    const float* wihr = (const float*)d_in[2];
    const float* wihi = (const float*)d_in[3];
    const float* wihj = (const float*)d_in[4];
    const float* wihk = (const float*)d_in[5];
    const float* whhr = (const float*)d_in[6];
    const float* whhi = (const float*)d_in[7];
    const float* whhj = (const float*)d_in[8];
    const float* whhk = (const float*)d_in[9];
    const float* bih  = (const float*)d_in[10];
    const float* bhh  = (const float*)d_in[11];
    float* out = (float*)d_out;

    qrn_prep<<<24, 256>>>(wihr, wihi, wihj, wihk, whhr, whhi, whhj, whhk);

    cudaFuncSetAttribute(qrn_gemm, cudaFuncAttributeMaxDynamicSharedMemorySize, GEMM_SMEM);
    qrn_gemm<<<148, 384, GEMM_SMEM>>>(x, bih);

    cudaFuncSetAttribute(qrn_recur, cudaFuncAttributeMaxDynamicSharedMemorySize, REC_SMEM);
    qrn_recur<<<128, 384, REC_SMEM>>>(hx, bhh, out, out_size);
}

// round 12
// speedup vs baseline: 1.0636x; 1.0636x over previous
#include <cuda_runtime.h>
#include <cuda_bf16.h>

#define TT 2048
#define BB 64
#define GG 192
#define OUT_MAIN 33554432
#define NTILE 8192

typedef unsigned long long ull;

// ---------------- device scratch (no cudaMalloc allowed) ----------------
__device__ float g_gi[(size_t)TT * BB * 768];          // input-side preactivations
__device__ ulonglong2 g_wihA[64 * 96];                 // {(r pair),(i pair)} per (u, col-pair)
__device__ ulonglong2 g_wihB[64 * 96];                 // {(j pair),(k pair)}
__device__ ulonglong2 g_whhA[64 * 96];
__device__ ulonglong2 g_whhB[64 * 96];

// ---------------- helpers ----------------
__device__ __forceinline__ ull pk2(float a, float b) {
    ull r; asm("mov.b64 %0, {%1,%2};" : "=l"(r) : "f"(a), "f"(b)); return r;
}
__device__ __forceinline__ float2 upk2(ull v) {
    float2 r; asm("mov.b64 {%0,%1}, %2;" : "=f"(r.x), "=f"(r.y) : "l"(v)); return r;
}
__device__ __forceinline__ unsigned s2u(const void* p) {
    unsigned a;
    asm("{ .reg .u64 t; cvta.to.shared.u64 t, %1; cvt.u32.u64 %0, t; }" : "=r"(a) : "l"(p));
    return a;
}
#define FMA2(acc, a, b) asm("fma.rn.f32x2 %0, %1, %2, %0;" : "+l"(acc) : "l"(a), "l"(b))

// Full quaternion (Hamilton) product contribution for one u and one column
// pair: 16 packed FMAs. P/N accumulator split avoids operand negation.
#define QFMA16(hr2,hi2,hj2,hk2, wr2,wi2,wj2,wk2, Pr,Nr,Pi,Ni,Pj,Nj,Pk,Nk) do { \
    FMA2(Pr,hr2,wr2); FMA2(Nr,hi2,wi2); FMA2(Nr,hj2,wj2); FMA2(Nr,hk2,wk2);    \
    FMA2(Pi,hr2,wi2); FMA2(Pi,hi2,wr2); FMA2(Pi,hk2,wj2); FMA2(Ni,hj2,wk2);    \
    FMA2(Pj,hr2,wj2); FMA2(Pj,hi2,wk2); FMA2(Pj,hj2,wr2); FMA2(Nj,hk2,wi2);    \
    FMA2(Pk,hr2,wk2); FMA2(Pk,hj2,wi2); FMA2(Pk,hk2,wr2); FMA2(Nk,hi2,wj2);    \
} while (0)

__device__ __forceinline__ float sig_f(float x) {
    return 1.0f / (1.0f + __expf(-x));
}
__device__ __forceinline__ float tanh_f(float x) {
    float e = __expf(2.0f * x);
    return 1.0f - 2.0f / (e + 1.0f);
}

// ---------------- weight packing ----------------
__global__ void qrn_prep(const float* __restrict__ wihr, const float* __restrict__ wihi,
                         const float* __restrict__ wihj, const float* __restrict__ wihk,
                         const float* __restrict__ whhr, const float* __restrict__ whhi,
                         const float* __restrict__ whhj, const float* __restrict__ whhk) {
    int idx = blockIdx.x * blockDim.x + threadIdx.x;
    if (idx >= 64 * 96) return;
    int u = idx / 96, jp = idx % 96;
    int c0 = u * GG + 2 * jp;
    ulonglong2 a, bv;
    a.x  = pk2(wihr[c0], wihr[c0 + 1]); a.y  = pk2(wihi[c0], wihi[c0 + 1]);
    bv.x = pk2(wihj[c0], wihj[c0 + 1]); bv.y = pk2(wihk[c0], wihk[c0 + 1]);
    g_wihA[idx] = a; g_wihB[idx] = bv;
    a.x  = pk2(whhr[c0], whhr[c0 + 1]); a.y  = pk2(whhi[c0], whhi[c0 + 1]);
    bv.x = pk2(whhj[c0], whhj[c0 + 1]); bv.y = pk2(whhk[c0], whhk[c0 + 1]);
    g_whhA[idx] = a; g_whhB[idx] = bv;
}

// ---------------- phase 1: gi = x @ W_ih + b_ih (full chip, serial) ----------------
#define GEMM_SMEM (98304 * 2 + 16384)
__global__ __launch_bounds__(384, 1) void qrn_gemm(const float* __restrict__ x,
                                                   const float* __restrict__ bih) {
    extern __shared__ char smem[];
    ulonglong2* swA = (ulonglong2*)smem;
    ulonglong2* swB = (ulonglong2*)(smem + 98304);
    float* xs = (float*)(smem + 196608);
    int t = threadIdx.x;
    for (int i = t; i < 6144; i += 384) { swA[i] = g_wihA[i]; swB[i] = g_wihB[i]; }
    int jp = t % 96, rg = t / 96;
    float2 bias2[4];
#pragma unroll
    for (int q = 0; q < 4; ++q) bias2[q] = *(const float2*)(bih + q * GG + 2 * jp);

    for (int tile = blockIdx.x; tile < NTILE; tile += gridDim.x) {
        __syncthreads();
        const float4* xt4 = (const float4*)(x + (size_t)tile * 4096);
        float4* xs4 = (float4*)xs;
        for (int i = t; i < 1024; i += 384) xs4[i] = xt4[i];
        __syncthreads();

        ull acc[4][8];
#pragma unroll
        for (int rr = 0; rr < 4; ++rr)
#pragma unroll
            for (int k = 0; k < 8; ++k) acc[rr][k] = 0ull;

#pragma unroll 4
        for (int u = 0; u < 64; ++u) {
            ulonglong2 wA = swA[u * 96 + jp];
            ulonglong2 wB = swB[u * 96 + jp];
#pragma unroll
            for (int rr = 0; rr < 4; ++rr) {
                const float* xr = xs + (rg * 4 + rr) * 256 + u;
                float hr = xr[0], hi = xr[64], hj = xr[128], hk = xr[192];
                ull hr2 = pk2(hr, hr), hi2 = pk2(hi, hi);
                ull hj2 = pk2(hj, hj), hk2 = pk2(hk, hk);
                QFMA16(hr2, hi2, hj2, hk2, wA.x, wA.y, wB.x, wB.y,
                       acc[rr][0], acc[rr][1], acc[rr][2], acc[rr][3],
                       acc[rr][4], acc[rr][5], acc[rr][6], acc[rr][7]);
            }
        }

#pragma unroll
        for (int rr = 0; rr < 4; ++rr) {
            float* go = g_gi + ((size_t)tile * 16 + rg * 4 + rr) * 768;
#pragma unroll
            for (int q = 0; q < 4; ++q) {
                float2 p = upk2(acc[rr][2 * q]);
                float2 n = upk2(acc[rr][2 * q + 1]);
                float2 o;
                o.x = p.x - n.x + bias2[q].x;
                o.y = p.y - n.y + bias2[q].y;
                *(float2*)(go + q * GG + 2 * jp) = o;
            }
        }
    }
}

// ---------------- phase 2: recurrence, 2-CTA cluster per batch (K-split) ----------------
// Rank r sums u in [32r, 32r+32) for ALL 768 columns. W_hh slice in REGISTERS.
// Warp layout: lane = partition(p = l>>3)*8 + colpair(l&7); partition reduction
// via 2x shfl_xor, so fully-reduced local sums leave the warp with no smem
// round-trip. Each thread then does ONE local ST.64 + ONE remote DSMEM ST.64
// (+arrive) for its p-component. red/pbuf use 200-float component stride
// (conflict-free). Owners wait on 384 peer arrivals, read 3+3 LDS, gate, done.
__global__ __launch_bounds__(384, 1) __cluster_dims__(2, 1, 1)
void qrn_recur(const float* __restrict__ hx, const float* __restrict__ bhh,
               float* __restrict__ out, int out_size) {
    __shared__ __align__(16) float red[800];         // full local-half sums (stride 200)
    __shared__ __align__(16) float pbuf[2 * 800];    // peer sums, x2 parity
    __shared__ __align__(16) float h4f[512];         // {h,h} dup pairs per (u,q)
    __shared__ __align__(8)  ull mbar[1];

    int t = threadIdx.x;
    unsigned rank;
    asm("mov.u32 %0, %%cluster_ctarank;" : "=r"(rank));
    int b = blockIdx.x >> 1;
    int w = t >> 5, l = t & 31;
    int p = l >> 3, jx = l & 7;
    int jp = w * 8 + jx;                 // col-pair 0..95
    int ru = (int)rank * 32;

    // register-resident W_hh slice: u = ru + p*8 + uu
    ulonglong2 wAr[8], wBr[8];
#pragma unroll
    for (int uu = 0; uu < 8; ++uu) {
        wAr[uu] = g_whhA[(ru + p * 8 + uu) * 96 + jp];
        wBr[uu] = g_whhB[(ru + p * 8 + uu) * 96 + jp];
    }

    unsigned mbar_u = s2u(mbar);
    unsigned pbuf_u = s2u(pbuf);
    unsigned peer = rank ^ 1u;
    unsigned peer_mbar, peer_pbuf;
    asm("mapa.shared::cluster.u32 %0, %1, %2;" : "=r"(peer_mbar) : "r"(mbar_u), "r"(peer));
    asm("mapa.shared::cluster.u32 %0, %1, %2;" : "=r"(peer_pbuf) : "r"(pbuf_u), "r"(peer));

    float hcur = 0.f, bh0 = 0.f, bh1 = 0.f, bh2 = 0.f;
    int q = 0, u = 0;
    if (t < 256) {
        q = t >> 6; u = t & 63;
        int o0g = q * GG + u;
        hcur = hx[b * 256 + t];
        float2 hd; hd.x = hcur; hd.y = hcur;
        *(float2*)(h4f + u * 8 + 2 * q) = hd;
        bh0 = bhh[o0g]; bh1 = bhh[o0g + 64]; bh2 = bhh[o0g + 128];
    }
    if (t == 0)
        asm volatile("mbarrier.init.shared.b64 [%0], %1;" :: "r"(mbar_u), "r"(384u) : "memory");
    __syncthreads();
    asm volatile("barrier.cluster.arrive.aligned;" ::: "memory");
    asm volatile("barrier.cluster.wait.aligned;" ::: "memory");

    // preload gi[0]
    float gc0 = 0.f, gc1 = 0.f, gc2 = 0.f;
    if (t < 256) {
        const float* gp = g_gi + (size_t)b * 768 + q * GG + u;
        gc0 = gp[0]; gc1 = gp[64]; gc2 = gp[128];
    }

#pragma unroll 1
    for (int step = 0; step < TT; ++step) {
        unsigned par = (unsigned)step & 1u;
        // prefetch gi[step+1] (covered by the whole step)
        float gn0 = 0.f, gn1 = 0.f, gn2 = 0.f;
        if (t < 256 && step + 1 < TT) {
            const float* gp = g_gi + ((size_t)(step + 1) * BB + b) * 768 + q * GG + u;
            gn0 = __ldcg(gp); gn1 = __ldcg(gp + 64); gn2 = __ldcg(gp + 128);
        }

        ull Pr = 0, Nr = 0, Pi = 0, Ni = 0, Pj = 0, Nj = 0, Pk = 0, Nk = 0;
#pragma unroll
        for (int uu = 0; uu < 8; ++uu) {
            int gu = ru + p * 8 + uu;
            ulonglong2 hA = *(ulonglong2*)(h4f + gu * 8);       // {hr,hr,hi,hi}
            ulonglong2 hB = *(ulonglong2*)(h4f + gu * 8 + 4);   // {hj,hj,hk,hk}
            QFMA16(hA.x, hA.y, hB.x, hB.y, wAr[uu].x, wAr[uu].y, wBr[uu].x, wBr[uu].y,
                   Pr, Nr, Pi, Ni, Pj, Nj, Pk, Nk);
        }
        // combine P/N, then in-warp partition reduction (xor 8, xor 16)
        float2 vr, vi, vj, vk;
        {
            float2 a, n2;
            a = upk2(Pr); n2 = upk2(Nr); vr.x = a.x - n2.x; vr.y = a.y - n2.y;
            a = upk2(Pi); n2 = upk2(Ni); vi.x = a.x - n2.x; vi.y = a.y - n2.y;
            a = upk2(Pj); n2 = upk2(Nj); vj.x = a.x - n2.x; vj.y = a.y - n2.y;
            a = upk2(Pk); n2 = upk2(Nk); vk.x = a.x - n2.x; vk.y = a.y - n2.y;
        }
#pragma unroll
        for (int m = 8; m <= 16; m <<= 1) {
            vr.x += __shfl_xor_sync(0xFFFFFFFFu, vr.x, m);
            vr.y += __shfl_xor_sync(0xFFFFFFFFu, vr.y, m);
            vi.x += __shfl_xor_sync(0xFFFFFFFFu, vi.x, m);
            vi.y += __shfl_xor_sync(0xFFFFFFFFu, vi.y, m);
            vj.x += __shfl_xor_sync(0xFFFFFFFFu, vj.x, m);
            vj.y += __shfl_xor_sync(0xFFFFFFFFu, vj.y, m);
            vk.x += __shfl_xor_sync(0xFFFFFFFFu, vk.x, m);
            vk.y += __shfl_xor_sync(0xFFFFFFFFu, vk.y, m);
        }
        // each lane keeps its p-component and publishes locally + to peer
        {
            float2 myv = (p == 0) ? vr : ((p == 1) ? vi : ((p == 2) ? vj : vk));
            int coff = p * 200 + 2 * jp;
            *(float2*)(red + coff) = myv;
            ull pv = pk2(myv.x, myv.y);
            unsigned dst = peer_pbuf + ((par * 800u + (unsigned)coff) << 2);
            asm volatile("st.shared::cluster.b64 [%0], %1;" :: "r"(dst), "l"(pv) : "memory");
            asm volatile("mbarrier.arrive.release.cluster.shared::cluster.b64 _, [%0];"
                         :: "r"(peer_mbar) : "memory");
        }
        __syncthreads();

        if (t < 256) {
            int o0 = q * 200 + u;
            // wait for peer's 384 arrivals on local mbar (acquire.cta: flag+data local)
            unsigned done = 0;
            while (!done)
                asm volatile("{ .reg .pred pp; "
                             "mbarrier.try_wait.parity.acquire.cta.shared::cta.b64 pp, [%1], %2, 0x989680; "
                             "selp.b32 %0, 1, 0, pp; }"
                             : "=r"(done) : "r"(mbar_u), "r"(par) : "memory");
            const float* pb = pbuf + par * 800;
            float gh0 = red[o0]       + pb[o0];
            float gh1 = red[o0 + 64]  + pb[o0 + 64];
            float gh2 = red[o0 + 128] + pb[o0 + 128];
            float rg_ = sig_f(gc0 + gh0 + bh0);
            float zg  = sig_f(gc1 + gh1 + bh1);
            float ng  = tanh_f(gc2 + rg_ * (gh2 + bh2));
            hcur = ng + zg * (hcur - ng);
            float2 hd; hd.x = hcur; hd.y = hcur;
            *(float2*)(h4f + u * 8 + 2 * q) = hd;
            if (rank == 0)
                out[((size_t)step * BB + b) * 256 + t] = hcur;
        }
        gc0 = gn0; gc1 = gn1; gc2 = gn2;
        __syncthreads();
    }

    if (rank == 0 && t < 256 && out_size >= OUT_MAIN + BB * 256)
        out[OUT_MAIN + b * 256 + t] = hcur;

    asm volatile("barrier.cluster.arrive.aligned;" ::: "memory");
    asm volatile("barrier.cluster.wait.aligned;" ::: "memory");
}

extern "C" void kernel_launch(void* const* d_in, const int* in_sizes, int n_in,
                              void* d_out, int out_size) {
    const float* x    = (const float*)d_in[0];
    const float* hx   = (const float*)d_in[1];
    const float* wihr = (const float*)d_in[2];
    const float* wihi = (const float*)d_in[3];
    const float* wihj = (const float*)d_in[4];
    const float* wihk = (const float*)d_in[5];
    const float* whhr = (const float*)d_in[6];
    const float* whhi = (const float*)d_in[7];
    const float* whhj = (const float*)d_in[8];
    const float* whhk = (const float*)d_in[9];
    const float* bih  = (const float*)d_in[10];
    const float* bhh  = (const float*)d_in[11];
    float* out = (float*)d_out;

    qrn_prep<<<24, 256>>>(wihr, wihi, wihj, wihk, whhr, whhi, whhj, whhk);

    cudaFuncSetAttribute(qrn_gemm, cudaFuncAttributeMaxDynamicSharedMemorySize, GEMM_SMEM);
    qrn_gemm<<<148, 384, GEMM_SMEM>>>(x, bih);

    qrn_recur<<<128, 384>>>(hx, bhh, out, out_size);
}

// round 14
// speedup vs baseline: 1.1858x; 1.1149x over previous
#include <cuda_runtime.h>
#include <cuda_bf16.h>
#include <mma.h>

using namespace nvcuda;

#define TT 2048
#define BB 64
#define GG 192
#define OUT_MAIN 33554432

typedef unsigned long long ull;

// ---------------- device scratch (no cudaMalloc allowed) ----------------
__device__ float g_gi[(size_t)TT * BB * 768];           // input-side preactivations (no bias)
__device__ __nv_bfloat16 g_Whi[256 * 768];              // Hamilton W_ih, bf16 high part
__device__ __nv_bfloat16 g_Wlo[256 * 768];              // bf16 low (residual) part
__device__ ulonglong2 g_whhA[64 * 96];                  // {(r pair),(i pair)} per (u, col-pair)
__device__ ulonglong2 g_whhB[64 * 96];                  // {(j pair),(k pair)}

// ---------------- helpers ----------------
__device__ __forceinline__ ull pk2(float a, float b) {
    ull r; asm("mov.b64 %0, {%1,%2};" : "=l"(r) : "f"(a), "f"(b)); return r;
}
__device__ __forceinline__ float2 upk2(ull v) {
    float2 r; asm("mov.b64 {%0,%1}, %2;" : "=f"(r.x), "=f"(r.y) : "l"(v)); return r;
}
__device__ __forceinline__ unsigned s2u(const void* p) {
    unsigned a;
    asm("{ .reg .u64 t; cvta.to.shared.u64 t, %1; cvt.u32.u64 %0, t; }" : "=r"(a) : "l"(p));
    return a;
}
#define FMA2(acc, a, b) asm("fma.rn.f32x2 %0, %1, %2, %0;" : "+l"(acc) : "l"(a), "l"(b))

// Full quaternion (Hamilton) product contribution for one u and one column
// pair: 16 packed FMAs. P/N accumulator split avoids operand negation.
#define QFMA16(hr2,hi2,hj2,hk2, wr2,wi2,wj2,wk2, Pr,Nr,Pi,Ni,Pj,Nj,Pk,Nk) do { \
    FMA2(Pr,hr2,wr2); FMA2(Nr,hi2,wi2); FMA2(Nr,hj2,wj2); FMA2(Nr,hk2,wk2);    \
    FMA2(Pi,hr2,wi2); FMA2(Pi,hi2,wr2); FMA2(Pi,hk2,wj2); FMA2(Ni,hj2,wk2);    \
    FMA2(Pj,hr2,wj2); FMA2(Pj,hi2,wk2); FMA2(Pj,hj2,wr2); FMA2(Nj,hk2,wi2);    \
    FMA2(Pk,hr2,wk2); FMA2(Pk,hj2,wi2); FMA2(Pk,hk2,wr2); FMA2(Nk,hi2,wj2);    \
} while (0)

__device__ __forceinline__ float sig_f(float x) {
    return 1.0f / (1.0f + __expf(-x));
}
__device__ __forceinline__ float tanh_f(float x) {
    float e = __expf(2.0f * x);
    return 1.0f - 2.0f / (e + 1.0f);
}

// ---------------- prep: Hamilton W_ih bf16 hi/lo + W_hh packing ----------------
__global__ void qrn_prep(const float* __restrict__ wihr, const float* __restrict__ wihi,
                         const float* __restrict__ wihj, const float* __restrict__ wihk,
                         const float* __restrict__ whhr, const float* __restrict__ whhi,
                         const float* __restrict__ whhj, const float* __restrict__ whhk) {
    int idx = blockIdx.x * blockDim.x + threadIdx.x;

    if (idx < 6144) {   // pack W_hh pairs for the recurrence
        int u = idx / 96, jp = idx % 96;
        int c0 = u * GG + 2 * jp;
        ulonglong2 a, bv;
        a.x  = pk2(whhr[c0], whhr[c0 + 1]); a.y  = pk2(whhi[c0], whhi[c0 + 1]);
        bv.x = pk2(whhj[c0], whhj[c0 + 1]); bv.y = pk2(whhk[c0], whhk[c0 + 1]);
        g_whhA[idx] = a; g_whhB[idx] = bv;
    }

    if (idx < 256 * 768) {  // build full 256x768 Hamilton W_ih, split bf16 hi/lo
        const int   cmp[16] = {0,1,2,3, 1,0,3,2, 2,3,0,1, 3,2,1,0};
        const float sgn[16] = {1,1,1,1, -1,1,1,-1, -1,-1,1,1, -1,1,-1,1};
        const float* wp[4] = {wihr, wihi, wihj, wihk};
        int row = idx / 768, col = idx % 768;
        int a = row >> 6, u = row & 63, bq = col / 192, c = col % 192;
        float w = sgn[a * 4 + bq] * wp[cmp[a * 4 + bq]][u * GG + c];
        __nv_bfloat16 hi = __float2bfloat16(w);
        float res = w - __bfloat162float(hi);
        g_Whi[idx] = hi;
        g_Wlo[idx] = __float2bfloat16(res);
    }
}

// ---------------- phase 1: gi = x @ W_ih  (bf16 split, tensor cores) ----------------
// CTA tile 128x128; grid (1024 M-tiles, 6 N-tiles); 8 warps as 4x2 of 32x64.
// A tile (128x256 fp32) -> smem bf16 hi/lo once; B (W) streamed in K=64 chunks.
// gi = Ahi*Bhi + Ahi*Blo + Alo*Bhi  (bias folded into the recurrence).
#define LDA 264
#define LDB 136
#define LDS_ 132
#define WG_SMEM (67584 + 67584 + 17408 + 17408)

__global__ __launch_bounds__(256, 1) void qrn_wgemm(const float* __restrict__ x) {
    extern __shared__ char gsm[];
    __nv_bfloat16* Ahi = (__nv_bfloat16*)gsm;
    __nv_bfloat16* Alo = (__nv_bfloat16*)(gsm + 67584);
    __nv_bfloat16* Bhi = (__nv_bfloat16*)(gsm + 135168);
    __nv_bfloat16* Blo = (__nv_bfloat16*)(gsm + 152576);
    float* stage = (float*)gsm;

    int t = threadIdx.x;
    int warp = t >> 5;
    int wr = warp >> 1, wc = warp & 1;       // 4x2 warp grid, 32x64 warp tile
    int tileM = blockIdx.x, tileN = blockIdx.y;

    // load A tile (128 rows x 256 cols fp32), convert to bf16 hi/lo
    {
        const float4* xg = (const float4*)(x + (size_t)tileM * 128 * 256);
        for (int i = t; i < 8192; i += 256) {
            float4 v = xg[i];
            int e = i * 4, row = e >> 8, col = e & 255;
            __nv_bfloat16 h0 = __float2bfloat16(v.x), h1 = __float2bfloat16(v.y);
            __nv_bfloat16 h2 = __float2bfloat16(v.z), h3 = __float2bfloat16(v.w);
            __nv_bfloat162 p01, p23;
            p01.x = h0; p01.y = h1; p23.x = h2; p23.y = h3;
            *(__nv_bfloat162*)(Ahi + row * LDA + col)     = p01;
            *(__nv_bfloat162*)(Ahi + row * LDA + col + 2) = p23;
            p01.x = __float2bfloat16(v.x - __bfloat162float(h0));
            p01.y = __float2bfloat16(v.y - __bfloat162float(h1));
            p23.x = __float2bfloat16(v.z - __bfloat162float(h2));
            p23.y = __float2bfloat16(v.w - __bfloat162float(h3));
            *(__nv_bfloat162*)(Alo + row * LDA + col)     = p01;
            *(__nv_bfloat162*)(Alo + row * LDA + col + 2) = p23;
        }
    }

    wmma::fragment<wmma::accumulator, 16, 16, 16, float> acc[2][4];
#pragma unroll
    for (int r = 0; r < 2; ++r)
#pragma unroll
        for (int c = 0; c < 4; ++c) wmma::fill_fragment(acc[r][c], 0.0f);

    int tn = tileN * 128;
    for (int kc = 0; kc < 4; ++kc) {
        int k0 = kc * 64;
        __syncthreads();
        // load B chunk 64x128 hi/lo
        for (int i = t; i < 4096; i += 256) {
            int e = i * 2, kk = e >> 7, c = e & 127;
            *(__nv_bfloat162*)(Bhi + kk * LDB + c) =
                *(const __nv_bfloat162*)(g_Whi + (size_t)(k0 + kk) * 768 + tn + c);
            *(__nv_bfloat162*)(Blo + kk * LDB + c) =
                *(const __nv_bfloat162*)(g_Wlo + (size_t)(k0 + kk) * 768 + tn + c);
        }
        __syncthreads();

#pragma unroll
        for (int ks = 0; ks < 4; ++ks) {
            int ka = k0 + ks * 16;
            wmma::fragment<wmma::matrix_a, 16, 16, 16, __nv_bfloat16, wmma::row_major> ah[2], al[2];
            wmma::fragment<wmma::matrix_b, 16, 16, 16, __nv_bfloat16, wmma::row_major> bh[4], bl[4];
#pragma unroll
            for (int r = 0; r < 2; ++r) {
                wmma::load_matrix_sync(ah[r], Ahi + (wr * 32 + r * 16) * LDA + ka, LDA);
                wmma::load_matrix_sync(al[r], Alo + (wr * 32 + r * 16) * LDA + ka, LDA);
            }
#pragma unroll
            for (int c = 0; c < 4; ++c) {
                wmma::load_matrix_sync(bh[c], Bhi + (ks * 16) * LDB + wc * 64 + c * 16, LDB);
                wmma::load_matrix_sync(bl[c], Blo + (ks * 16) * LDB + wc * 64 + c * 16, LDB);
            }
#pragma unroll
            for (int r = 0; r < 2; ++r)
#pragma unroll
                for (int c = 0; c < 4; ++c) {
                    wmma::mma_sync(acc[r][c], ah[r], bh[c], acc[r][c]);
                    wmma::mma_sync(acc[r][c], ah[r], bl[c], acc[r][c]);
                    wmma::mma_sync(acc[r][c], al[r], bh[c], acc[r][c]);
                }
        }
    }

    __syncthreads();   // done reading A; reuse its smem as fp32 staging
#pragma unroll
    for (int r = 0; r < 2; ++r)
#pragma unroll
        for (int c = 0; c < 4; ++c)
            wmma::store_matrix_sync(stage + (wr * 32 + r * 16) * LDS_ + wc * 64 + c * 16,
                                    acc[r][c], LDS_, wmma::mem_row_major);
    __syncthreads();

    {
        float* go = g_gi + (size_t)tileM * 128 * 768 + tn;
        for (int i = t; i < 4096; i += 256) {
            int e = i * 4, row = e >> 7, col = e & 127;
            float4 v = *(float4*)(stage + row * LDS_ + col);
            *(float4*)(go + (size_t)row * 768 + col) = v;
        }
    }
}

// ---------------- phase 2: recurrence, 2-CTA cluster per batch (K-split) ----------------
// R9 structure verbatim (best known): rank r sums u in [32r,32r+32) for all 768
// columns, W_hh slice in registers, 4-partition smem reduction, owner-side DSMEM
// partial exchange, acquire.cta wait. b_ih folded into per-thread bias registers.
__global__ __launch_bounds__(384, 1) __cluster_dims__(2, 1, 1)
void qrn_recur(const float* __restrict__ hx, const float* __restrict__ bhh,
               const float* __restrict__ bih,
               float* __restrict__ out, int out_size) {
    __shared__ __align__(16) float red[4 * 768];     // 12KB: 4 partition partials
    __shared__ __align__(16) float h4dup[512];       // 2KB: {h,h} dup pairs per (u,q)
    __shared__ __align__(16) float pbuf[2 * 768];    // 6KB: peer partials, x2 parity
    __shared__ __align__(8)  ull mbar[1];

    int t = threadIdx.x;
    unsigned rank;
    asm("mov.u32 %0, %%cluster_ctarank;" : "=r"(rank));
    int b = blockIdx.x >> 1;
    int jp = t % 96, up = t / 96, ub = up * 8;
    int ru = (int)rank * 32;

    // register-resident W_hh slice: u = ru + ub + uu
    ulonglong2 wAr[8], wBr[8];
#pragma unroll
    for (int uu = 0; uu < 8; ++uu) {
        wAr[uu] = g_whhA[(ru + ub + uu) * 96 + jp];
        wBr[uu] = g_whhB[(ru + ub + uu) * 96 + jp];
    }

    unsigned mbar_u = s2u(mbar);
    unsigned pbuf_u = s2u(pbuf);
    unsigned peer = rank ^ 1u;
    unsigned peer_mbar, peer_pbuf;
    asm("mapa.shared::cluster.u32 %0, %1, %2;" : "=r"(peer_mbar) : "r"(mbar_u), "r"(peer));
    asm("mapa.shared::cluster.u32 %0, %1, %2;" : "=r"(peer_pbuf) : "r"(pbuf_u), "r"(peer));

    float hcur = 0.f, bc0 = 0.f, bc1 = 0.f, bi2 = 0.f, bh2 = 0.f;
    int q = 0, u = 0, o0 = 0;
    if (t < 256) {
        q = t >> 6; u = t & 63; o0 = q * GG + u;
        hcur = hx[b * 256 + t];
        h4dup[u * 8 + 2 * q]     = hcur;
        h4dup[u * 8 + 2 * q + 1] = hcur;
        bc0 = bhh[o0] + bih[o0];
        bc1 = bhh[o0 + 64] + bih[o0 + 64];
        bi2 = bih[o0 + 128];
        bh2 = bhh[o0 + 128];
    }
    if (t == 0)
        asm volatile("mbarrier.init.shared.b64 [%0], %1;" :: "r"(mbar_u), "r"(256u) : "memory");
    __syncthreads();
    asm volatile("barrier.cluster.arrive.aligned;" ::: "memory");
    asm volatile("barrier.cluster.wait.aligned;" ::: "memory");

    // preload gi[0]
    float gc0 = 0.f, gc1 = 0.f, gc2 = 0.f;
    if (t < 256) {
        const float* gp = g_gi + (size_t)b * 768 + o0;
        gc0 = gp[0]; gc1 = gp[64]; gc2 = gp[128];
    }

#pragma unroll 1
    for (int step = 0; step < TT; ++step) {
        unsigned par = (unsigned)step & 1u;
        // prefetch gi[step+1] (covered by the whole step)
        float gn0 = 0.f, gn1 = 0.f, gn2 = 0.f;
        if (t < 256 && step + 1 < TT) {
            const float* gp = g_gi + ((size_t)(step + 1) * BB + b) * 768 + o0;
            gn0 = __ldcg(gp); gn1 = __ldcg(gp + 64); gn2 = __ldcg(gp + 128);
        }

        ull Pr = 0, Nr = 0, Pi = 0, Ni = 0, Pj = 0, Nj = 0, Pk = 0, Nk = 0;
#pragma unroll
        for (int uu = 0; uu < 8; ++uu) {
            int gu = ru + ub + uu;
            ulonglong2 hA = *(ulonglong2*)(h4dup + gu * 8);       // {hr,hr,hi,hi}
            ulonglong2 hB = *(ulonglong2*)(h4dup + gu * 8 + 4);   // {hj,hj,hk,hk}
            QFMA16(hA.x, hA.y, hB.x, hB.y, wAr[uu].x, wAr[uu].y, wBr[uu].x, wBr[uu].y,
                   Pr, Nr, Pi, Ni, Pj, Nj, Pk, Nk);
        }
        {
            float2 pr = upk2(Pr), nr = upk2(Nr), pi = upk2(Pi), ni = upk2(Ni);
            float2 pj = upk2(Pj), nj = upk2(Nj), pk = upk2(Pk), nk = upk2(Nk);
            float* rb = red + up * 768 + 2 * jp;
            float2 v;
            v.x = pr.x - nr.x; v.y = pr.y - nr.y; *(float2*)(rb)       = v;
            v.x = pi.x - ni.x; v.y = pi.y - ni.y; *(float2*)(rb + 192) = v;
            v.x = pj.x - nj.x; v.y = pj.y - nj.y; *(float2*)(rb + 384) = v;
            v.x = pk.x - nk.x; v.y = pk.y - nk.y; *(float2*)(rb + 576) = v;
        }
        __syncthreads();

        if (t < 256) {
            // local half-sum for this output
            float p0 = red[o0]       + red[768 + o0]       + red[1536 + o0]       + red[2304 + o0];
            float p1 = red[o0 + 64]  + red[768 + o0 + 64]  + red[1536 + o0 + 64]  + red[2304 + o0 + 64];
            float p2 = red[o0 + 128] + red[768 + o0 + 128] + red[1536 + o0 + 128] + red[2304 + o0 + 128];
            // ship to peer (parity-buffered), then signal peer's mbar (release)
            unsigned dst = peer_pbuf + ((par * 768u + (unsigned)o0) << 2);
            asm volatile("st.shared::cluster.b32 [%0], %1;" :: "r"(dst),        "r"(__float_as_uint(p0)) : "memory");
            asm volatile("st.shared::cluster.b32 [%0], %1;" :: "r"(dst + 256u), "r"(__float_as_uint(p1)) : "memory");
            asm volatile("st.shared::cluster.b32 [%0], %1;" :: "r"(dst + 512u), "r"(__float_as_uint(p2)) : "memory");
            asm volatile("mbarrier.arrive.release.cluster.shared::cluster.b64 _, [%0];"
                         :: "r"(peer_mbar) : "memory");
            // wait for peer's 256 arrivals on local mbar (acquire.cta: flag+data local)
            unsigned done = 0;
            while (!done)
                asm volatile("{ .reg .pred p; "
                             "mbarrier.try_wait.parity.acquire.cta.shared::cta.b64 p, [%1], %2, 0x989680; "
                             "selp.b32 %0, 1, 0, p; }"
                             : "=r"(done) : "r"(mbar_u), "r"(par) : "memory");
            const float* pb = pbuf + par * 768;
            float gh0 = p0 + pb[o0];
            float gh1 = p1 + pb[o0 + 64];
            float gh2 = p2 + pb[o0 + 128];
            float rg_ = sig_f(gc0 + gh0 + bc0);
            float zg  = sig_f(gc1 + gh1 + bc1);
            float ng  = tanh_f(gc2 + bi2 + rg_ * (gh2 + bh2));
            hcur = ng + zg * (hcur - ng);
            float2 hd; hd.x = hcur; hd.y = hcur;
            *(float2*)(h4dup + u * 8 + 2 * q) = hd;
            if (rank == 0)
                out[((size_t)step * BB + b) * 256 + t] = hcur;
        }
        gc0 = gn0; gc1 = gn1; gc2 = gn2;
        __syncthreads();
    }

    if (rank == 0 && t < 256 && out_size >= OUT_MAIN + BB * 256)
        out[OUT_MAIN + b * 256 + t] = hcur;

    asm volatile("barrier.cluster.arrive.aligned;" ::: "memory");
    asm volatile("barrier.cluster.wait.aligned;" ::: "memory");
}

extern "C" void kernel_launch(void* const* d_in, const int* in_sizes, int n_in,
                              void* d_out, int out_size) {
    const float* x    = (const float*)d_in[0];
    const float* hx   = (const float*)d_in[1];
    const float* wihr = (const float*)d_in[2];
    const float* wihi = (const float*)d_in[3];
    const float* wihj = (const float*)d_in[4];
    const float* wihk = (const float*)d_in[5];
    const float* whhr = (const float*)d_in[6];
    const float* whhi = (const float*)d_in[7];
    const float* whhj = (const float*)d_in[8];
    const float* whhk = (const float*)d_in[9];
    const float* bih  = (const float*)d_in[10];
    const float* bhh  = (const float*)d_in[11];
    float* out = (float*)d_out;

    qrn_prep<<<768, 256>>>(wihr, wihi, wihj, wihk, whhr, whhi, whhj, whhk);

    cudaFuncSetAttribute(qrn_wgemm, cudaFuncAttributeMaxDynamicSharedMemorySize, WG_SMEM);
    qrn_wgemm<<<dim3(1024, 6), 256, WG_SMEM>>>(x);

    qrn_recur<<<128, 384>>>(hx, bhh, bih, out, out_size);
}

// round 17
// speedup vs baseline: 1.2053x; 1.0164x over previous
#include <cuda_runtime.h>
#include <cuda_bf16.h>
#include <mma.h>

using namespace nvcuda;

#define TT 2048
#define BB 64
#define GG 192
#define OUT_MAIN 33554432

typedef unsigned long long ull;

// ---------------- device scratch (no cudaMalloc allowed) ----------------
__device__ float g_gi[(size_t)TT * BB * 768];           // input-side preactivations (no bias)
__device__ __nv_bfloat16 g_Whi[256 * 768];              // Hamilton W_ih, bf16 high part
__device__ __nv_bfloat16 g_Wlo[256 * 768];              // bf16 low (residual) part
__device__ __nv_bfloat16 g_xhi[(size_t)TT * BB * 256];  // x, bf16 high part
__device__ __nv_bfloat16 g_xlo[(size_t)TT * BB * 256];  // x, bf16 low part
__device__ ulonglong2 g_whhA[64 * 96];                  // {(r pair),(i pair)} per (u, col-pair)
__device__ ulonglong2 g_whhB[64 * 96];                  // {(j pair),(k pair)}

// ---------------- helpers ----------------
__device__ __forceinline__ ull pk2(float a, float b) {
    ull r; asm("mov.b64 %0, {%1,%2};" : "=l"(r) : "f"(a), "f"(b)); return r;
}
__device__ __forceinline__ float2 upk2(ull v) {
    float2 r; asm("mov.b64 {%0,%1}, %2;" : "=f"(r.x), "=f"(r.y) : "l"(v)); return r;
}
__device__ __forceinline__ unsigned s2u(const void* p) {
    unsigned a;
    asm("{ .reg .u64 t; cvta.to.shared.u64 t, %1; cvt.u32.u64 %0, t; }" : "=r"(a) : "l"(p));
    return a;
}
#define FMA2(acc, a, b) asm("fma.rn.f32x2 %0, %1, %2, %0;" : "+l"(acc) : "l"(a), "l"(b))

#define QFMA16(hr2,hi2,hj2,hk2, wr2,wi2,wj2,wk2, Pr,Nr,Pi,Ni,Pj,Nj,Pk,Nk) do { \
    FMA2(Pr,hr2,wr2); FMA2(Nr,hi2,wi2); FMA2(Nr,hj2,wj2); FMA2(Nr,hk2,wk2);    \
    FMA2(Pi,hr2,wi2); FMA2(Pi,hi2,wr2); FMA2(Pi,hk2,wj2); FMA2(Ni,hj2,wk2);    \
    FMA2(Pj,hr2,wj2); FMA2(Pj,hi2,wk2); FMA2(Pj,hj2,wr2); FMA2(Nj,hk2,wi2);    \
    FMA2(Pk,hr2,wk2); FMA2(Pk,hj2,wi2); FMA2(Pk,hk2,wr2); FMA2(Nk,hi2,wj2);    \
} while (0)

__device__ __forceinline__ float sig_f(float x) {
    return 1.0f / (1.0f + __expf(-x));
}
__device__ __forceinline__ float tanh_f(float x) {
    float e = __expf(2.0f * x);
    return 1.0f - 2.0f / (e + 1.0f);
}

// ---------------- prep: Hamilton W_ih bf16 hi/lo + W_hh packing ----------------
__global__ void qrn_prep(const float* __restrict__ wihr, const float* __restrict__ wihi,
                         const float* __restrict__ wihj, const float* __restrict__ wihk,
                         const float* __restrict__ whhr, const float* __restrict__ whhi,
                         const float* __restrict__ whhj, const float* __restrict__ whhk) {
    int idx = blockIdx.x * blockDim.x + threadIdx.x;

    if (idx < 6144) {   // pack W_hh pairs for the recurrence
        int u = idx / 96, jp = idx % 96;
        int c0 = u * GG + 2 * jp;
        ulonglong2 a, bv;
        a.x  = pk2(whhr[c0], whhr[c0 + 1]); a.y  = pk2(whhi[c0], whhi[c0 + 1]);
        bv.x = pk2(whhj[c0], whhj[c0 + 1]); bv.y = pk2(whhk[c0], whhk[c0 + 1]);
        g_whhA[idx] = a; g_whhB[idx] = bv;
    }

    if (idx < 256 * 768) {  // build full 256x768 Hamilton W_ih, split bf16 hi/lo
        const int   cmp[16] = {0,1,2,3, 1,0,3,2, 2,3,0,1, 3,2,1,0};
        const float sgn[16] = {1,1,1,1, -1,1,1,-1, -1,-1,1,1, -1,1,-1,1};
        const float* wp[4] = {wihr, wihi, wihj, wihk};
        int row = idx / 768, col = idx % 768;
        int a = row >> 6, u = row & 63, bq = col / 192, c = col % 192;
        float w = sgn[a * 4 + bq] * wp[cmp[a * 4 + bq]][u * GG + c];
        __nv_bfloat16 hi = __float2bfloat16(w);
        float res = w - __bfloat162float(hi);
        g_Whi[idx] = hi;
        g_Wlo[idx] = __float2bfloat16(res);
    }
}

// ---------------- x split: fp32 -> bf16 hi/lo (one pass, DRAM-bound) ----------------
__global__ __launch_bounds__(1024) void qrn_xsplit(const float* __restrict__ x) {
    size_t i = (size_t)blockIdx.x * 1024 + threadIdx.x;   // over float4, 8388608 total
    const float4* x4 = (const float4*)x;
    float4 v = x4[i];
    __nv_bfloat16 h0 = __float2bfloat16(v.x), h1 = __float2bfloat16(v.y);
    __nv_bfloat16 h2 = __float2bfloat16(v.z), h3 = __float2bfloat16(v.w);
    __nv_bfloat16 l0 = __float2bfloat16(v.x - __bfloat162float(h0));
    __nv_bfloat16 l1 = __float2bfloat16(v.y - __bfloat162float(h1));
    __nv_bfloat16 l2 = __float2bfloat16(v.z - __bfloat162float(h2));
    __nv_bfloat16 l3 = __float2bfloat16(v.w - __bfloat162float(h3));
    ushort4 hp, lp;
    hp.x = *(unsigned short*)&h0; hp.y = *(unsigned short*)&h1;
    hp.z = *(unsigned short*)&h2; hp.w = *(unsigned short*)&h3;
    lp.x = *(unsigned short*)&l0; lp.y = *(unsigned short*)&l1;
    lp.z = *(unsigned short*)&l2; lp.w = *(unsigned short*)&l3;
    ((ushort4*)g_xhi)[i] = hp;
    ((ushort4*)g_xlo)[i] = lp;
}

// ---------------- phase 1: gi = x @ W_ih  (bf16 split, tensor cores) ----------------
// CTA tile 128x128; 512 threads = 16 warps as 4x4 grid of 32x32 warp tiles.
// A (pre-split bf16) copied once to smem; B double-buffered via registers.
// gi = Ahi*Bhi + Ahi*Blo + Alo*Bhi  (bias folded into the recurrence).
#define LDA 264
#define LDB 136
#define LDS_ 132
#define A_MAT 67584
#define B_MAT 17408
#define B_BUF (2 * B_MAT)
#define WG_SMEM (2 * A_MAT + 2 * B_BUF)   // 135168 + 69632 = 204800

__global__ __launch_bounds__(512, 1) void qrn_wgemm() {
    extern __shared__ char gsm[];
    __nv_bfloat16* Ahi = (__nv_bfloat16*)gsm;
    __nv_bfloat16* Alo = (__nv_bfloat16*)(gsm + A_MAT);
    float* stage = (float*)gsm;

    int t = threadIdx.x;
    int warp = t >> 5;
    int wr = warp >> 2, wc = warp & 3;       // 4x4 warp grid, 32x32 warp tiles
    int tileM = blockIdx.x;
    int tn = blockIdx.y * 128;

    // B chunk loader: chunk kc = rows [kc*64, kc*64+64) of W, cols [tn, tn+128)
    const int4* bh4 = (const int4*)(g_Whi + tn);
    const int4* bl4 = (const int4*)(g_Wlo + tn);
    int bi0 = t * 2, bi1 = t * 2 + 1;                    // 2048 int4 per chunk (hi+lo)
    int br0 = bi0 >> 4, bc0 = bi0 & 15;                  // row (0..63), col int4 (0..15)
    int br1 = bi1 >> 4, bc1 = bi1 & 15;
    // W row stride in int4 = 768/8 = 96

    // A copy: 128 rows x 256 bf16 = 4096 int4 per matrix
    {
        const int4* xh4 = (const int4*)(g_xhi + (size_t)tileM * 128 * 256);
        const int4* xl4 = (const int4*)(g_xlo + (size_t)tileM * 128 * 256);
        for (int i = t; i < 4096; i += 512) {
            int row = i >> 5, col8 = (i & 31) * 8;
            *(int4*)(Ahi + row * LDA + col8) = xh4[i];
            *(int4*)(Alo + row * LDA + col8) = xl4[i];
        }
    }
    // prefetch B chunk 0 to regs, store to buffer 0
    int4 nh0, nh1, nl0, nl1;
    nh0 = bh4[br0 * 96 + bc0]; nh1 = bh4[br1 * 96 + bc1];
    nl0 = bl4[br0 * 96 + bc0]; nl1 = bl4[br1 * 96 + bc1];
    {
        __nv_bfloat16* Bh = (__nv_bfloat16*)(gsm + 2 * A_MAT);
        __nv_bfloat16* Bl = Bh + B_MAT / 2;
        *(int4*)(Bh + br0 * LDB + bc0 * 8) = nh0;
        *(int4*)(Bh + br1 * LDB + bc1 * 8) = nh1;
        *(int4*)(Bl + br0 * LDB + bc0 * 8) = nl0;
        *(int4*)(Bl + br1 * LDB + bc1 * 8) = nl1;
    }
    __syncthreads();

    wmma::fragment<wmma::accumulator, 16, 16, 16, float> acc[2][2];
#pragma unroll
    for (int r = 0; r < 2; ++r)
#pragma unroll
        for (int c = 0; c < 2; ++c) wmma::fill_fragment(acc[r][c], 0.0f);

#pragma unroll
    for (int kc = 0; kc < 4; ++kc) {
        // prefetch next B chunk to regs (latency hidden under compute)
        if (kc < 3) {
            const int4* nbh = bh4 + (size_t)(kc + 1) * 64 * 96;
            const int4* nbl = bl4 + (size_t)(kc + 1) * 64 * 96;
            nh0 = nbh[br0 * 96 + bc0]; nh1 = nbh[br1 * 96 + bc1];
            nl0 = nbl[br0 * 96 + bc0]; nl1 = nbl[br1 * 96 + bc1];
        }
        __nv_bfloat16* Bh = (__nv_bfloat16*)(gsm + 2 * A_MAT + (kc & 1) * B_BUF);
        __nv_bfloat16* Bl = Bh + B_MAT / 2;

#pragma unroll
        for (int ks = 0; ks < 4; ++ks) {
            int ka = kc * 64 + ks * 16;
            wmma::fragment<wmma::matrix_a, 16, 16, 16, __nv_bfloat16, wmma::row_major> ah[2], al[2];
            wmma::fragment<wmma::matrix_b, 16, 16, 16, __nv_bfloat16, wmma::row_major> bh[2], bl[2];
#pragma unroll
            for (int r = 0; r < 2; ++r) {
                wmma::load_matrix_sync(ah[r], Ahi + (wr * 32 + r * 16) * LDA + ka, LDA);
                wmma::load_matrix_sync(al[r], Alo + (wr * 32 + r * 16) * LDA + ka, LDA);
            }
#pragma unroll
            for (int c = 0; c < 2; ++c) {
                wmma::load_matrix_sync(bh[c], Bh + (ks * 16) * LDB + wc * 32 + c * 16, LDB);
                wmma::load_matrix_sync(bl[c], Bl + (ks * 16) * LDB + wc * 32 + c * 16, LDB);
            }
#pragma unroll
            for (int r = 0; r < 2; ++r)
#pragma unroll
                for (int c = 0; c < 2; ++c) {
                    wmma::mma_sync(acc[r][c], ah[r], bh[c], acc[r][c]);
                    wmma::mma_sync(acc[r][c], ah[r], bl[c], acc[r][c]);
                    wmma::mma_sync(acc[r][c], al[r], bh[c], acc[r][c]);
                }
        }
        __syncthreads();
        if (kc < 3) {
            __nv_bfloat16* Bh2 = (__nv_bfloat16*)(gsm + 2 * A_MAT + ((kc + 1) & 1) * B_BUF);
            __nv_bfloat16* Bl2 = Bh2 + B_MAT / 2;
            *(int4*)(Bh2 + br0 * LDB + bc0 * 8) = nh0;
            *(int4*)(Bh2 + br1 * LDB + bc1 * 8) = nh1;
            *(int4*)(Bl2 + br0 * LDB + bc0 * 8) = nl0;
            *(int4*)(Bl2 + br1 * LDB + bc1 * 8) = nl1;
            __syncthreads();
        }
    }

    // epilogue: stage in fp32 (reuses A smem), then coalesced global stores
#pragma unroll
    for (int r = 0; r < 2; ++r)
#pragma unroll
        for (int c = 0; c < 2; ++c)
            wmma::store_matrix_sync(stage + (wr * 32 + r * 16) * LDS_ + wc * 32 + c * 16,
                                    acc[r][c], LDS_, wmma::mem_row_major);
    __syncthreads();
    {
        float* go = g_gi + (size_t)tileM * 128 * 768 + tn;
        for (int i = t; i < 4096; i += 512) {
            int e = i * 4, row = e >> 7, col = e & 127;
            float4 v = *(float4*)(stage + row * LDS_ + col);
            *(float4*)(go + (size_t)row * 768 + col) = v;
        }
    }
}

// ---------------- phase 2: recurrence, 2-CTA cluster per batch (K-split) ----------------
// R9/R14 structure verbatim (best known). b_ih folded into bias registers.
__global__ __launch_bounds__(384, 1) __cluster_dims__(2, 1, 1)
void qrn_recur(const float* __restrict__ hx, const float* __restrict__ bhh,
               const float* __restrict__ bih,
               float* __restrict__ out, int out_size) {
    __shared__ __align__(16) float red[4 * 768];     // 12KB: 4 partition partials
    __shared__ __align__(16) float h4dup[512];       // 2KB: {h,h} dup pairs per (u,q)
    __shared__ __align__(16) float pbuf[2 * 768];    // 6KB: peer partials, x2 parity
    __shared__ __align__(8)  ull mbar[1];

    int t = threadIdx.x;
    unsigned rank;
    asm("mov.u32 %0, %%cluster_ctarank;" : "=r"(rank));
    int b = blockIdx.x >> 1;
    int jp = t % 96, up = t / 96, ub = up * 8;
    int ru = (int)rank * 32;

    ulonglong2 wAr[8], wBr[8];
#pragma unroll
    for (int uu = 0; uu < 8; ++uu) {
        wAr[uu] = g_whhA[(ru + ub + uu) * 96 + jp];
        wBr[uu] = g_whhB[(ru + ub + uu) * 96 + jp];
    }

    unsigned mbar_u = s2u(mbar);
    unsigned pbuf_u = s2u(pbuf);
    unsigned peer = rank ^ 1u;
    unsigned peer_mbar, peer_pbuf;
    asm("mapa.shared::cluster.u32 %0, %1, %2;" : "=r"(peer_mbar) : "r"(mbar_u), "r"(peer));
    asm("mapa.shared::cluster.u32 %0, %1, %2;" : "=r"(peer_pbuf) : "r"(pbuf_u), "r"(peer));

    float hcur = 0.f, bc0 = 0.f, bc1 = 0.f, bi2 = 0.f, bh2 = 0.f;
    int q = 0, u = 0, o0 = 0;
    if (t < 256) {
        q = t >> 6; u = t & 63; o0 = q * GG + u;
        hcur = hx[b * 256 + t];
        h4dup[u * 8 + 2 * q]     = hcur;
        h4dup[u * 8 + 2 * q + 1] = hcur;
        bc0 = bhh[o0] + bih[o0];
        bc1 = bhh[o0 + 64] + bih[o0 + 64];
        bi2 = bih[o0 + 128];
        bh2 = bhh[o0 + 128];
    }
    if (t == 0)
        asm volatile("mbarrier.init.shared.b64 [%0], %1;" :: "r"(mbar_u), "r"(256u) : "memory");
    __syncthreads();
    asm volatile("barrier.cluster.arrive.aligned;" ::: "memory");
    asm volatile("barrier.cluster.wait.aligned;" ::: "memory");

    float gc0 = 0.f, gc1 = 0.f, gc2 = 0.f;
    if (t < 256) {
        const float* gp = g_gi + (size_t)b * 768 + o0;
        gc0 = gp[0]; gc1 = gp[64]; gc2 = gp[128];
    }

#pragma unroll 1
    for (int step = 0; step < TT; ++step) {
        unsigned par = (unsigned)step & 1u;
        float gn0 = 0.f, gn1 = 0.f, gn2 = 0.f;
        if (t < 256 && step + 1 < TT) {
            const float* gp = g_gi + ((size_t)(step + 1) * BB + b) * 768 + o0;
            gn0 = __ldcg(gp); gn1 = __ldcg(gp + 64); gn2 = __ldcg(gp + 128);
        }

        ull Pr = 0, Nr = 0, Pi = 0, Ni = 0, Pj = 0, Nj = 0, Pk = 0, Nk = 0;
#pragma unroll
        for (int uu = 0; uu < 8; ++uu) {
            int gu = ru + ub + uu;
            ulonglong2 hA = *(ulonglong2*)(h4dup + gu * 8);
            ulonglong2 hB = *(ulonglong2*)(h4dup + gu * 8 + 4);
            QFMA16(hA.x, hA.y, hB.x, hB.y, wAr[uu].x, wAr[uu].y, wBr[uu].x, wBr[uu].y,
                   Pr, Nr, Pi, Ni, Pj, Nj, Pk, Nk);
        }
        {
            float2 pr = upk2(Pr), nr = upk2(Nr), pi = upk2(Pi), ni = upk2(Ni);
            float2 pj = upk2(Pj), nj = upk2(Nj), pk = upk2(Pk), nk = upk2(Nk);
            float* rb = red + up * 768 + 2 * jp;
            float2 v;
            v.x = pr.x - nr.x; v.y = pr.y - nr.y; *(float2*)(rb)       = v;
            v.x = pi.x - ni.x; v.y = pi.y - ni.y; *(float2*)(rb + 192) = v;
            v.x = pj.x - nj.x; v.y = pj.y - nj.y; *(float2*)(rb + 384) = v;
            v.x = pk.x - nk.x; v.y = pk.y - nk.y; *(float2*)(rb + 576) = v;
        }
        __syncthreads();

        if (t < 256) {
            float p0 = red[o0]       + red[768 + o0]       + red[1536 + o0]       + red[2304 + o0];
            float p1 = red[o0 + 64]  + red[768 + o0 + 64]  + red[1536 + o0 + 64]  + red[2304 + o0 + 64];
            float p2 = red[o0 + 128] + red[768 + o0 + 128] + red[1536 + o0 + 128] + red[2304 + o0 + 128];
            unsigned dst = peer_pbuf + ((par * 768u + (unsigned)o0) << 2);
            asm volatile("st.shared::cluster.b32 [%0], %1;" :: "r"(dst),        "r"(__float_as_uint(p0)) : "memory");
            asm volatile("st.shared::cluster.b32 [%0], %1;" :: "r"(dst + 256u), "r"(__float_as_uint(p1)) : "memory");
            asm volatile("st.shared::cluster.b32 [%0], %1;" :: "r"(dst + 512u), "r"(__float_as_uint(p2)) : "memory");
            asm volatile("mbarrier.arrive.release.cluster.shared::cluster.b64 _, [%0];"
                         :: "r"(peer_mbar) : "memory");
            unsigned done = 0;
            while (!done)
                asm volatile("{ .reg .pred p; "
                             "mbarrier.try_wait.parity.acquire.cta.shared::cta.b64 p, [%1], %2, 0x989680; "
                             "selp.b32 %0, 1, 0, p; }"
                             : "=r"(done) : "r"(mbar_u), "r"(par) : "memory");
            const float* pb = pbuf + par * 768;
            float gh0 = p0 + pb[o0];
            float gh1 = p1 + pb[o0 + 64];
            float gh2 = p2 + pb[o0 + 128];
            float rg_ = sig_f(gc0 + gh0 + bc0);
            float zg  = sig_f(gc1 + gh1 + bc1);
            float ng  = tanh_f(gc2 + bi2 + rg_ * (gh2 + bh2));
            hcur = ng + zg * (hcur - ng);
            float2 hd; hd.x = hcur; hd.y = hcur;
            *(float2*)(h4dup + u * 8 + 2 * q) = hd;
            if (rank == 0)
                out[((size_t)step * BB + b) * 256 + t] = hcur;
        }
        gc0 = gn0; gc1 = gn1; gc2 = gn2;
        __syncthreads();
    }

    if (rank == 0 && t < 256 && out_size >= OUT_MAIN + BB * 256)
        out[OUT_MAIN + b * 256 + t] = hcur;

    asm volatile("barrier.cluster.arrive.aligned;" ::: "memory");
    asm volatile("barrier.cluster.wait.aligned;" ::: "memory");
}

extern "C" void kernel_launch(void* const* d_in, const int* in_sizes, int n_in,
                              void* d_out, int out_size) {
    const float* x    = (const float*)d_in[0];
    const float* hx   = (const float*)d_in[1];
    const float* wihr = (const float*)d_in[2];
    const float* wihi = (const float*)d_in[3];
    const float* wihj = (const float*)d_in[4];
    const float* wihk = (const float*)d_in[5];
    const float* whhr = (const float*)d_in[6];
    const float* whhi = (const float*)d_in[7];
    const float* whhj = (const float*)d_in[8];
    const float* whhk = (const float*)d_in[9];
    const float* bih  = (const float*)d_in[10];
    const float* bhh  = (const float*)d_in[11];
    float* out = (float*)d_out;

    qrn_prep<<<768, 256>>>(wihr, wihi, wihj, wihk, whhr, whhi, whhj, whhk);
    qrn_xsplit<<<8192, 1024>>>(x);

    cudaFuncSetAttribute(qrn_wgemm, cudaFuncAttributeMaxDynamicSharedMemorySize, WG_SMEM);
    qrn_wgemm<<<dim3(1024, 6), 512, WG_SMEM>>>();

    qrn_recur<<<128, 384>>>(hx, bhh, bih, out, out_size);
}